// round 2
// baseline (speedup 1.0000x reference)
#include <cuda_runtime.h>

#define Nn 256
#define Dd 64
#define Cc 32
#define Rr 16
#define Oo 32

// lse[d,o,r] = max_{ij} logits + log(sum_ij exp(logits - max))
__device__ float g_lse[Dd * Oo * Rr];

__global__ void lse_kernel(const float* __restrict__ logits) {
    __shared__ float red[8];
    __shared__ float bmax;
    const int b = blockIdx.x;  // flat (d,o,r); logits[d,o,r,:,:] is 1024 contiguous floats
    const float4 v = reinterpret_cast<const float4*>(logits)[(size_t)b * 256 + threadIdx.x];
    float m = fmaxf(fmaxf(v.x, v.y), fmaxf(v.z, v.w));
#pragma unroll
    for (int o = 16; o; o >>= 1) m = fmaxf(m, __shfl_xor_sync(0xffffffffu, m, o));
    if ((threadIdx.x & 31) == 0) red[threadIdx.x >> 5] = m;
    __syncthreads();
    if (threadIdx.x == 0) {
        float t = red[0];
#pragma unroll
        for (int k = 1; k < 8; k++) t = fmaxf(t, red[k]);
        bmax = t;
    }
    __syncthreads();
    m = bmax;
    float s = __expf(v.x - m) + __expf(v.y - m) + __expf(v.z - m) + __expf(v.w - m);
#pragma unroll
    for (int o = 16; o; o >>= 1) s += __shfl_xor_sync(0xffffffffu, s, o);
    __syncthreads();  // red[] reuse
    if ((threadIdx.x & 31) == 0) red[threadIdx.x >> 5] = s;
    __syncthreads();
    if (threadIdx.x == 0) {
        float t = 0.f;
#pragma unroll
        for (int k = 0; k < 8; k++) t += red[k];
        g_lse[b] = m + logf(t);
    }
}

// One CTA per (d, r, n_half). Computes out[n, d, :, r] for 128 n values.
// smem: Lp/Rp hold exp(x - rowmax), stored transposed [i][n] for conflict-free
// stride-1 n access. Weights streamed per-i as a 32x32 [j][o] slab, double-buffered,
// with softmax applied on the fly via precomputed lse.
__global__ __launch_bounds__(256, 2)
void einsum_kernel(const float* __restrict__ left, const float* __restrict__ right,
                   const float* __restrict__ logits, float* __restrict__ out) {
    __shared__ float Lp[Cc * 128];
    __shared__ float Rp[Cc * 128];
    __shared__ float Ws[2 * Cc * Oo];
    __shared__ float lmaxs[128];
    __shared__ float rmaxs[128];

    const int b = blockIdx.x;      // ((d * Rr) + r) * 2 + nh
    const int nh = b & 1;
    const int r = (b >> 1) & (Rr - 1);
    const int d = b >> 5;
    const int tid = threadIdx.x;

    // ---- phase 1: rowmax + exp, transposed into smem ----
    {
        const int n_loc = tid & 127;
        const int n = nh * 128 + n_loc;
        const float* src = (tid < 128) ? left : right;
        float* dst = (tid < 128) ? Lp : Rp;
        float* mx = (tid < 128) ? lmaxs : rmaxs;
        const float* p = src + (size_t)n * (Dd * Cc * Rr) + d * (Cc * Rr) + r;
        float m = -3.4e38f;
#pragma unroll
        for (int i = 0; i < Cc; i++) m = fmaxf(m, p[i * Rr]);
        mx[n_loc] = m;
#pragma unroll
        for (int i = 0; i < Cc; i++) dst[i * 128 + n_loc] = __expf(p[i * Rr] - m);
    }

    // ---- phase 2: register-tiled contraction (2 n x 8 o per thread) ----
    const int to = (tid & 3) * 8;        // o0: 4 o-groups of 8
    const int tn = (tid >> 2) * 2;       // n0: 64 n-groups of 2

    // weight staging responsibility: thread loads 4 consecutive j for one o
    const int wo = tid >> 3;             // 0..31
    const int wj = (tid & 7) * 4;        // 0,4,...,28
    const float* wsrc = logits + ((size_t)(d * Oo + wo) * Rr + r) * (Cc * Cc) + wj;
    const float lseo = g_lse[(d * Oo + wo) * Rr + r];

    float acc[2][8];
#pragma unroll
    for (int q = 0; q < 2; q++)
#pragma unroll
        for (int w = 0; w < 8; w++) acc[q][w] = 0.f;

    for (int i = 0; i < Cc; i++) {
        float* wsb = Ws + (i & 1) * (Cc * Oo);
        const float4 lv = *reinterpret_cast<const float4*>(wsrc + i * Cc);
        wsb[(wj + 0) * Oo + wo] = __expf(lv.x - lseo);
        wsb[(wj + 1) * Oo + wo] = __expf(lv.y - lseo);
        wsb[(wj + 2) * Oo + wo] = __expf(lv.z - lseo);
        wsb[(wj + 3) * Oo + wo] = __expf(lv.w - lseo);
        __syncthreads();

        const float2 l2 = *reinterpret_cast<const float2*>(&Lp[i * 128 + tn]);
#pragma unroll
        for (int j = 0; j < Cc; j++) {
            const float2 r2 = *reinterpret_cast<const float2*>(&Rp[j * 128 + tn]);
            const float4 wa = *reinterpret_cast<const float4*>(&wsb[j * Oo + to]);
            const float4 wb = *reinterpret_cast<const float4*>(&wsb[j * Oo + to + 4]);
            const float p0 = l2.x * r2.x;
            const float p1 = l2.y * r2.y;
            acc[0][0] = fmaf(p0, wa.x, acc[0][0]);
            acc[0][1] = fmaf(p0, wa.y, acc[0][1]);
            acc[0][2] = fmaf(p0, wa.z, acc[0][2]);
            acc[0][3] = fmaf(p0, wa.w, acc[0][3]);
            acc[0][4] = fmaf(p0, wb.x, acc[0][4]);
            acc[0][5] = fmaf(p0, wb.y, acc[0][5]);
            acc[0][6] = fmaf(p0, wb.z, acc[0][6]);
            acc[0][7] = fmaf(p0, wb.w, acc[0][7]);
            acc[1][0] = fmaf(p1, wa.x, acc[1][0]);
            acc[1][1] = fmaf(p1, wa.y, acc[1][1]);
            acc[1][2] = fmaf(p1, wa.z, acc[1][2]);
            acc[1][3] = fmaf(p1, wa.w, acc[1][3]);
            acc[1][4] = fmaf(p1, wb.x, acc[1][4]);
            acc[1][5] = fmaf(p1, wb.y, acc[1][5]);
            acc[1][6] = fmaf(p1, wb.z, acc[1][6]);
            acc[1][7] = fmaf(p1, wb.w, acc[1][7]);
        }
        __syncthreads();
    }

    // ---- epilogue: log + add maxes, store (N, D, O, R) layout ----
#pragma unroll
    for (int q = 0; q < 2; q++) {
        const int n_loc = tn + q;
        const int n = nh * 128 + n_loc;
        const float add = lmaxs[n_loc] + rmaxs[n_loc];
        float* ob = out + (size_t)n * (Dd * Oo * Rr) + d * (Oo * Rr) + r;
#pragma unroll
        for (int w = 0; w < 8; w++)
            ob[(to + w) * Rr] = __logf(acc[q][w]) + add;
    }
}

extern "C" void kernel_launch(void* const* d_in, const int* in_sizes, int n_in,
                              void* d_out, int out_size) {
    const float* left = (const float*)d_in[0];
    const float* right = (const float*)d_in[1];
    const float* logits = (const float*)d_in[2];
    float* out = (float*)d_out;

    lse_kernel<<<Dd * Oo * Rr, 256>>>(logits);
    einsum_kernel<<<Dd * Rr * 2, 256>>>(left, right, logits, out);
}

// round 4
// speedup vs baseline: 5.3638x; 5.3638x over previous
#include <cuda_runtime.h>
#include <cuda_fp16.h>
#include <cstdint>

#define Nn 256
#define Dd 64
#define Cc 32
#define Rr 16
#define Oo 32

// softmax weights, fp16, [d][o][r][i*32+j]
__device__ __half g_BH[(size_t)Dd * Oo * Rr * 1024];
// exp(x - rowmax), fp16, [d][r][n][c]
__device__ __half g_LpH[(size_t)Dd * Rr * Nn * Cc];
__device__ __half g_RpH[(size_t)Dd * Rr * Nn * Cc];
// lmax + rmax, [d][r][n]
__device__ float g_msum[Dd * Rr * Nn];
// log-prob scratch, [d][r][o][n]  (coalesced for the GEMM, transposed later)
__device__ float g_scr[(size_t)Dd * Rr * Oo * Nn];

// ---------------- kernel A: softmax of logits -> fp16 weights ----------------
__global__ void bexp_kernel(const float* __restrict__ logits) {
    __shared__ float red[8];
    __shared__ float bmax, bsum;
    const int b = blockIdx.x;  // (d*Oo+o)*Rr+r : 1024 contiguous floats
    const float4 v = reinterpret_cast<const float4*>(logits)[(size_t)b * 256 + threadIdx.x];
    float m = fmaxf(fmaxf(v.x, v.y), fmaxf(v.z, v.w));
#pragma unroll
    for (int o = 16; o; o >>= 1) m = fmaxf(m, __shfl_xor_sync(~0u, m, o));
    if ((threadIdx.x & 31) == 0) red[threadIdx.x >> 5] = m;
    __syncthreads();
    if (threadIdx.x == 0) {
        float t = red[0];
#pragma unroll
        for (int k = 1; k < 8; k++) t = fmaxf(t, red[k]);
        bmax = t;
    }
    __syncthreads();
    m = bmax;
    const float e0 = __expf(v.x - m), e1 = __expf(v.y - m);
    const float e2 = __expf(v.z - m), e3 = __expf(v.w - m);
    float s = e0 + e1 + e2 + e3;
#pragma unroll
    for (int o = 16; o; o >>= 1) s += __shfl_xor_sync(~0u, s, o);
    __syncthreads();
    if ((threadIdx.x & 31) == 0) red[threadIdx.x >> 5] = s;
    __syncthreads();
    if (threadIdx.x == 0) {
        float t = 0.f;
#pragma unroll
        for (int k = 0; k < 8; k++) t += red[k];
        bsum = t;
    }
    __syncthreads();
    const float inv = 1.0f / bsum;
    __half2* dst = reinterpret_cast<__half2*>(g_BH) + (size_t)b * 512 + threadIdx.x * 2;
    dst[0] = __floats2half2_rn(e0 * inv, e1 * inv);
    dst[1] = __floats2half2_rn(e2 * inv, e3 * inv);
}

// ---------------- kernel B: left/right -> rowmax-shifted exp (fp16) ----------------
// 128 threads = 4 warps, each warp handles one (n,d) pair (32 c-lanes).
__global__ __launch_bounds__(128) void prep_kernel(const float* __restrict__ left,
                                                   const float* __restrict__ right) {
    __shared__ float sL[4][Cc * 17], sR[4][Cc * 17];
    __shared__ float lmaxs[4][Rr], rmaxs[4][Rr];
    const int w = threadIdx.x >> 5;
    const int n = blockIdx.x >> 4;
    const int d = (blockIdx.x & 15) * 4 + w;
    const int c = threadIdx.x & 31;
    float lv[Rr], rv[Rr];
    const float4* lp = reinterpret_cast<const float4*>(left + ((size_t)(n * Dd + d) * Cc + c) * Rr);
    const float4* rp = reinterpret_cast<const float4*>(right + ((size_t)(n * Dd + d) * Cc + c) * Rr);
#pragma unroll
    for (int q = 0; q < 4; q++) {
        *reinterpret_cast<float4*>(&lv[q * 4]) = lp[q];
        *reinterpret_cast<float4*>(&rv[q * 4]) = rp[q];
    }
#pragma unroll
    for (int rr = 0; rr < Rr; rr++) { sL[w][c * 17 + rr] = lv[rr]; sR[w][c * 17 + rr] = rv[rr]; }
    __syncwarp();
    if (c < 16) {
        float m = -3.4e38f;
        for (int cc = 0; cc < Cc; cc++) m = fmaxf(m, sL[w][cc * 17 + c]);
        lmaxs[w][c] = m;
    } else {
        const int rr = c - 16;
        float m = -3.4e38f;
        for (int cc = 0; cc < Cc; cc++) m = fmaxf(m, sR[w][cc * 17 + rr]);
        rmaxs[w][rr] = m;
    }
    __syncwarp();
#pragma unroll
    for (int rr = 0; rr < Rr; rr++) {
        const size_t base = ((size_t)(d * Rr + rr) * Nn + n) * Cc + c;
        g_LpH[base] = __float2half_rn(__expf(lv[rr] - lmaxs[w][rr]));
        g_RpH[base] = __float2half_rn(__expf(rv[rr] - rmaxs[w][rr]));
    }
    if (c < 16) g_msum[(d * Rr + c) * Nn + n] = lmaxs[w][c] + rmaxs[w][c];
}

// ---------------- kernel C: warp-MMA batched GEMM ----------------
__device__ __forceinline__ uint32_t s2u(const void* p) {
    uint32_t a;
    asm("{ .reg .u64 t; cvta.to.shared.u64 t, %1; cvt.u32.u64 %0, t; }" : "=r"(a) : "l"(p));
    return a;
}
__device__ __forceinline__ void ldmx4(uint32_t* a, uint32_t addr) {
    asm volatile("ldmatrix.sync.aligned.m8n8.x4.shared.b16 {%0,%1,%2,%3}, [%4];"
                 : "=r"(a[0]), "=r"(a[1]), "=r"(a[2]), "=r"(a[3]) : "r"(addr));
}
__device__ __forceinline__ void mma16816(float* c, const uint32_t* a, uint32_t b0, uint32_t b1) {
    asm volatile(
        "mma.sync.aligned.m16n8k16.row.col.f32.f16.f16.f32 "
        "{%0,%1,%2,%3},{%4,%5,%6,%7},{%8,%9},{%0,%1,%2,%3};"
        : "+f"(c[0]), "+f"(c[1]), "+f"(c[2]), "+f"(c[3])
        : "r"(a[0]), "r"(a[1]), "r"(a[2]), "r"(a[3]), "r"(b0), "r"(b1));
}

#define WSTRIDE 1032  // halves per padded W row (2064 B)

__global__ __launch_bounds__(512) void einsum_mma_kernel() {
    extern __shared__ __align__(16) __half smW[];  // 32 x 1032 halves
    const int tid = threadIdx.x;
    const int wid = tid >> 5;
    const int ln = tid & 31;
    const int b = blockIdx.x;  // d*16 + r
    const int r = b & 15;
    const int d = b >> 4;

    // ---- stage W (32 o-rows x 1024 halves) into padded smem ----
#pragma unroll
    for (int rr2 = 0; rr2 < 2; rr2++) {
        const int o = wid * 2 + rr2;
        const uint4* src = reinterpret_cast<const uint4*>(
                               g_BH + ((size_t)(d * Oo + o) * Rr + r) * 1024) + ln;
        uint4* dst = reinterpret_cast<uint4*>(smW + o * WSTRIDE) + ln;
#pragma unroll
        for (int u = 0; u < 4; u++) dst[u * 32] = src[u * 32];
    }

    // ---- per-lane operands ----
    const int wb = wid * 16;
    const int n0 = wb + (ln >> 2);
    const int n1 = n0 + 8;
    __half2 lp0[16], lp1[16];
    {
        const uint4* l0 = reinterpret_cast<const uint4*>(g_LpH + ((size_t)b * Nn + n0) * Cc);
        const uint4* l1 = reinterpret_cast<const uint4*>(g_LpH + ((size_t)b * Nn + n1) * Cc);
#pragma unroll
        for (int q = 0; q < 4; q++) {
            *reinterpret_cast<uint4*>(&lp0[q * 4]) = l0[q];
            *reinterpret_cast<uint4*>(&lp1[q * 4]) = l1[q];
        }
    }
    __half2 rp0[4], rp1[4];
    {
        const __half* r0 = g_RpH + ((size_t)b * Nn + n0) * Cc + (ln & 3) * 2;
        const __half* r1 = g_RpH + ((size_t)b * Nn + n1) * Cc + (ln & 3) * 2;
#pragma unroll
        for (int q = 0; q < 4; q++) {
            rp0[q] = *reinterpret_cast<const __half2*>(r0 + q * 8);
            rp1[q] = *reinterpret_cast<const __half2*>(r1 + q * 8);
        }
    }
    __syncthreads();

    float acc[2][2][4];
#pragma unroll
    for (int mt = 0; mt < 2; mt++)
#pragma unroll
        for (int nt = 0; nt < 2; nt++)
#pragma unroll
            for (int q = 0; q < 4; q++) acc[mt][nt][q] = 0.f;

    // ldmatrix lane address: row (ln&15), col-half (ln>>4)*8
    const uint32_t abase = s2u(smW) + ((uint32_t)(ln & 15) * WSTRIDE + (uint32_t)((ln >> 4) & 1) * 8) * 2;

#pragma unroll
    for (int kc = 0; kc < 64; kc++) {  // k16-tile: i = kc>>1, j0 = (kc&1)*16
        uint32_t a0[4], a1[4];
        ldmx4(a0, abase + (uint32_t)kc * 32);
        ldmx4(a1, abase + 16u * WSTRIDE * 2u + (uint32_t)kc * 32);
        const __half h0 = ((kc >> 1) & 1) ? __high2half(lp0[kc >> 2]) : __low2half(lp0[kc >> 2]);
        const __half h1 = ((kc >> 1) & 1) ? __high2half(lp1[kc >> 2]) : __low2half(lp1[kc >> 2]);
        const __half2 l20 = __half2half2(h0);
        const __half2 l21 = __half2half2(h1);
        const int q0 = (kc & 1) * 2;
        const __half2 b00 = __hmul2(rp0[q0], l20), b01 = __hmul2(rp0[q0 + 1], l20);
        const __half2 b10 = __hmul2(rp1[q0], l21), b11 = __hmul2(rp1[q0 + 1], l21);
        const uint32_t u00 = *reinterpret_cast<const uint32_t*>(&b00);
        const uint32_t u01 = *reinterpret_cast<const uint32_t*>(&b01);
        const uint32_t u10 = *reinterpret_cast<const uint32_t*>(&b10);
        const uint32_t u11 = *reinterpret_cast<const uint32_t*>(&b11);
        mma16816(acc[0][0], a0, u00, u01);
        mma16816(acc[0][1], a0, u10, u11);
        mma16816(acc[1][0], a1, u00, u01);
        mma16816(acc[1][1], a1, u10, u11);
    }

    // ---- epilogue: log + msum, write scratch [b][o][n] (n-coalesced) ----
#pragma unroll
    for (int mt = 0; mt < 2; mt++)
#pragma unroll
        for (int nt = 0; nt < 2; nt++) {
            const int o = mt * 16 + (ln >> 2);
            const int n = wb + nt * 8 + (ln & 3) * 2;
            const float2 ms = *reinterpret_cast<const float2*>(&g_msum[b * Nn + n]);
            float2 v0, v1;
            v0.x = __logf(acc[mt][nt][0]) + ms.x;
            v0.y = __logf(acc[mt][nt][1]) + ms.y;
            v1.x = __logf(acc[mt][nt][2]) + ms.x;
            v1.y = __logf(acc[mt][nt][3]) + ms.y;
            float* p = g_scr + ((size_t)b * Oo + o) * Nn + n;
            *reinterpret_cast<float2*>(p) = v0;
            *reinterpret_cast<float2*>(p + 8 * Nn) = v1;
        }
}

// ---------------- kernel D: transpose scratch [d][r][o][n] -> out [n][d][o][r] ----------------
__global__ __launch_bounds__(256) void transpose_kernel(float* __restrict__ out) {
    extern __shared__ __align__(16) float tile[];  // [512][33], idx = o*16+r
    const int d = blockIdx.x >> 3;
    const int nb = blockIdx.x & 7;
    const int tid = threadIdx.x;
#pragma unroll
    for (int it = 0; it < 16; it++) {
        const int gidx = it * 256 + tid;        // 0..4095
        const int ro = gidx >> 3, s4 = gidx & 7;  // ro = r*32+o
        const float4 v = *reinterpret_cast<const float4*>(
            g_scr + ((size_t)(d * 512 + ro)) * Nn + nb * 32 + s4 * 4);
        const int idx = (ro & 31) * 16 + (ro >> 5);  // o*16 + r
        float* t = &tile[idx * 33 + s4 * 4];
        t[0] = v.x; t[1] = v.y; t[2] = v.z; t[3] = v.w;
    }
    __syncthreads();
#pragma unroll
    for (int n = 0; n < 32; n++) {
        float* ob = out + ((size_t)(nb * 32 + n) * Dd + d) * 512;
        ob[tid] = tile[tid * 33 + n];
        ob[tid + 256] = tile[(tid + 256) * 33 + n];
    }
}

extern "C" void kernel_launch(void* const* d_in, const int* in_sizes, int n_in,
                              void* d_out, int out_size) {
    const float* left = (const float*)d_in[0];
    const float* right = (const float*)d_in[1];
    const float* logits = (const float*)d_in[2];
    float* out = (float*)d_out;

    bexp_kernel<<<Dd * Oo * Rr, 256>>>(logits);
    prep_kernel<<<Nn * Dd / 4, 128>>>(left, right);
    cudaFuncSetAttribute(einsum_mma_kernel, cudaFuncAttributeMaxDynamicSharedMemorySize, 32 * WSTRIDE * 2);
    einsum_mma_kernel<<<Dd * Rr, 512, 32 * WSTRIDE * 2>>>();
    cudaFuncSetAttribute(transpose_kernel, cudaFuncAttributeMaxDynamicSharedMemorySize, 512 * 33 * 4);
    transpose_kernel<<<Dd * 8, 256, 512 * 33 * 4>>>(out);
}

// round 5
// speedup vs baseline: 6.7256x; 1.2539x over previous
#include <cuda_runtime.h>
#include <cuda_fp16.h>
#include <cstdint>

#define Nn 256
#define Dd 64
#define Cc 32
#define Rr 16
#define Oo 32

// exp(x - rowmax), fp16, [d][r][n][c]
__device__ __half g_LpH[(size_t)Dd * Rr * Nn * Cc];
__device__ __half g_RpH[(size_t)Dd * Rr * Nn * Cc];
// lmax + rmax, [d][r][n]
__device__ float g_msum[Dd * Rr * Nn];
// log-prob scratch, [d][r][o][n]  (coalesced for the GEMM, transposed later; L2-resident)
__device__ float g_scr[(size_t)Dd * Rr * Oo * Nn];

// ---------------- kernel B: left/right -> rowmax-shifted exp (fp16) ----------------
// 128 threads = 4 warps, each warp handles one (n,d) pair (32 c-lanes).
__global__ __launch_bounds__(128) void prep_kernel(const float* __restrict__ left,
                                                   const float* __restrict__ right) {
    __shared__ float sL[4][Cc * 17], sR[4][Cc * 17];
    __shared__ float lmaxs[4][Rr], rmaxs[4][Rr];
    const int w = threadIdx.x >> 5;
    const int n = blockIdx.x >> 4;
    const int d = (blockIdx.x & 15) * 4 + w;
    const int c = threadIdx.x & 31;
    float lv[Rr], rv[Rr];
    const float4* lp = reinterpret_cast<const float4*>(left + ((size_t)(n * Dd + d) * Cc + c) * Rr);
    const float4* rp = reinterpret_cast<const float4*>(right + ((size_t)(n * Dd + d) * Cc + c) * Rr);
#pragma unroll
    for (int q = 0; q < 4; q++) {
        *reinterpret_cast<float4*>(&lv[q * 4]) = lp[q];
        *reinterpret_cast<float4*>(&rv[q * 4]) = rp[q];
    }
#pragma unroll
    for (int rr = 0; rr < Rr; rr++) { sL[w][c * 17 + rr] = lv[rr]; sR[w][c * 17 + rr] = rv[rr]; }
    __syncwarp();
    if (c < 16) {
        float m = -3.4e38f;
        for (int cc = 0; cc < Cc; cc++) m = fmaxf(m, sL[w][cc * 17 + c]);
        lmaxs[w][c] = m;
    } else {
        const int rr = c - 16;
        float m = -3.4e38f;
        for (int cc = 0; cc < Cc; cc++) m = fmaxf(m, sR[w][cc * 17 + rr]);
        rmaxs[w][rr] = m;
    }
    __syncwarp();
#pragma unroll
    for (int rr = 0; rr < Rr; rr++) {
        const size_t base = ((size_t)(d * Rr + rr) * Nn + n) * Cc + c;
        g_LpH[base] = __float2half_rn(__expf(lv[rr] - lmaxs[w][rr]));
        g_RpH[base] = __float2half_rn(__expf(rv[rr] - rmaxs[w][rr]));
    }
    if (c < 16) g_msum[(d * Rr + c) * Nn + n] = lmaxs[w][c] + rmaxs[w][c];
}

// ---------------- kernel C: warp-MMA batched GEMM with fused softmax staging ----------------
__device__ __forceinline__ uint32_t s2u(const void* p) {
    uint32_t a;
    asm("{ .reg .u64 t; cvta.to.shared.u64 t, %1; cvt.u32.u64 %0, t; }" : "=r"(a) : "l"(p));
    return a;
}
__device__ __forceinline__ void ldmx4(uint32_t* a, uint32_t addr) {
    asm volatile("ldmatrix.sync.aligned.m8n8.x4.shared.b16 {%0,%1,%2,%3}, [%4];"
                 : "=r"(a[0]), "=r"(a[1]), "=r"(a[2]), "=r"(a[3]) : "r"(addr));
}
__device__ __forceinline__ void mma16816(float* c, const uint32_t* a, uint32_t b0, uint32_t b1) {
    asm volatile(
        "mma.sync.aligned.m16n8k16.row.col.f32.f16.f16.f32 "
        "{%0,%1,%2,%3},{%4,%5,%6,%7},{%8,%9},{%0,%1,%2,%3};"
        : "+f"(c[0]), "+f"(c[1]), "+f"(c[2]), "+f"(c[3])
        : "r"(a[0]), "r"(a[1]), "r"(a[2]), "r"(a[3]), "r"(b0), "r"(b1));
}

#define WSTRIDE 1032  // halves per padded W row (2064 B)

__global__ __launch_bounds__(512) void einsum_mma_kernel(const float* __restrict__ logits) {
    extern __shared__ __align__(16) __half smW[];  // 32 x 1032 halves
    const int tid = threadIdx.x;
    const int wid = tid >> 5;
    const int ln = tid & 31;
    const int b = blockIdx.x;  // d*16 + r
    const int r = b & 15;
    const int d = b >> 4;

    // ---- stage W: per-warp fused softmax of logits[d, o, r, :] -> fp16 smem ----
#pragma unroll
    for (int rr2 = 0; rr2 < 2; rr2++) {
        const int o = wid * 2 + rr2;
        const float4* src = reinterpret_cast<const float4*>(
            logits + (((size_t)(d * Oo + o) * Rr + r) << 10));
        float4 v[8];
#pragma unroll
        for (int u = 0; u < 8; u++) v[u] = src[u * 32 + ln];
        float m = -3.4e38f;
#pragma unroll
        for (int u = 0; u < 8; u++)
            m = fmaxf(m, fmaxf(fmaxf(v[u].x, v[u].y), fmaxf(v[u].z, v[u].w)));
#pragma unroll
        for (int t = 16; t; t >>= 1) m = fmaxf(m, __shfl_xor_sync(~0u, m, t));
        float s = 0.f;
#pragma unroll
        for (int u = 0; u < 8; u++) {
            v[u].x = __expf(v[u].x - m);
            v[u].y = __expf(v[u].y - m);
            v[u].z = __expf(v[u].z - m);
            v[u].w = __expf(v[u].w - m);
            s += (v[u].x + v[u].y) + (v[u].z + v[u].w);
        }
#pragma unroll
        for (int t = 16; t; t >>= 1) s += __shfl_xor_sync(~0u, s, t);
        const float inv = 1.0f / s;
#pragma unroll
        for (int u = 0; u < 8; u++) {
            const __half2 h0 = __floats2half2_rn(v[u].x * inv, v[u].y * inv);
            const __half2 h1 = __floats2half2_rn(v[u].z * inv, v[u].w * inv);
            uint2 wv;
            wv.x = *reinterpret_cast<const uint32_t*>(&h0);
            wv.y = *reinterpret_cast<const uint32_t*>(&h1);
            *reinterpret_cast<uint2*>(smW + o * WSTRIDE + (u * 32 + ln) * 4) = wv;
        }
    }

    // ---- per-lane operands ----
    const int wb = wid * 16;
    const int n0 = wb + (ln >> 2);
    const int n1 = n0 + 8;
    __half2 lp0[16], lp1[16];
    {
        const uint4* l0 = reinterpret_cast<const uint4*>(g_LpH + ((size_t)b * Nn + n0) * Cc);
        const uint4* l1 = reinterpret_cast<const uint4*>(g_LpH + ((size_t)b * Nn + n1) * Cc);
#pragma unroll
        for (int q = 0; q < 4; q++) {
            *reinterpret_cast<uint4*>(&lp0[q * 4]) = l0[q];
            *reinterpret_cast<uint4*>(&lp1[q * 4]) = l1[q];
        }
    }
    __half2 rp0[4], rp1[4];
    {
        const __half* r0 = g_RpH + ((size_t)b * Nn + n0) * Cc + (ln & 3) * 2;
        const __half* r1 = g_RpH + ((size_t)b * Nn + n1) * Cc + (ln & 3) * 2;
#pragma unroll
        for (int q = 0; q < 4; q++) {
            rp0[q] = *reinterpret_cast<const __half2*>(r0 + q * 8);
            rp1[q] = *reinterpret_cast<const __half2*>(r1 + q * 8);
        }
    }
    __syncthreads();

    float acc[2][2][4];
#pragma unroll
    for (int mt = 0; mt < 2; mt++)
#pragma unroll
        for (int nt = 0; nt < 2; nt++)
#pragma unroll
            for (int q = 0; q < 4; q++) acc[mt][nt][q] = 0.f;

    // ldmatrix lane address: row (ln&15), col-half (ln>>4)*8
    const uint32_t abase = s2u(smW) + ((uint32_t)(ln & 15) * WSTRIDE + (uint32_t)((ln >> 4) & 1) * 8) * 2;

#pragma unroll
    for (int kc = 0; kc < 64; kc++) {  // k16-tile: i = kc>>1, j0 = (kc&1)*16
        uint32_t a0[4], a1[4];
        ldmx4(a0, abase + (uint32_t)kc * 32);
        ldmx4(a1, abase + 16u * WSTRIDE * 2u + (uint32_t)kc * 32);
        const __half h0 = ((kc >> 1) & 1) ? __high2half(lp0[kc >> 2]) : __low2half(lp0[kc >> 2]);
        const __half h1 = ((kc >> 1) & 1) ? __high2half(lp1[kc >> 2]) : __low2half(lp1[kc >> 2]);
        const __half2 l20 = __half2half2(h0);
        const __half2 l21 = __half2half2(h1);
        const int q0 = (kc & 1) * 2;
        const __half2 b00 = __hmul2(rp0[q0], l20), b01 = __hmul2(rp0[q0 + 1], l20);
        const __half2 b10 = __hmul2(rp1[q0], l21), b11 = __hmul2(rp1[q0 + 1], l21);
        const uint32_t u00 = *reinterpret_cast<const uint32_t*>(&b00);
        const uint32_t u01 = *reinterpret_cast<const uint32_t*>(&b01);
        const uint32_t u10 = *reinterpret_cast<const uint32_t*>(&b10);
        const uint32_t u11 = *reinterpret_cast<const uint32_t*>(&b11);
        mma16816(acc[0][0], a0, u00, u01);
        mma16816(acc[0][1], a0, u10, u11);
        mma16816(acc[1][0], a1, u00, u01);
        mma16816(acc[1][1], a1, u10, u11);
    }

    // ---- epilogue: log + msum, write scratch [b][o][n] (n-coalesced) ----
#pragma unroll
    for (int mt = 0; mt < 2; mt++)
#pragma unroll
        for (int nt = 0; nt < 2; nt++) {
            const int o = mt * 16 + (ln >> 2);
            const int n = wb + nt * 8 + (ln & 3) * 2;
            const float2 ms = *reinterpret_cast<const float2*>(&g_msum[b * Nn + n]);
            float2 v0, v1;
            v0.x = __logf(acc[mt][nt][0]) + ms.x;
            v0.y = __logf(acc[mt][nt][1]) + ms.y;
            v1.x = __logf(acc[mt][nt][2]) + ms.x;
            v1.y = __logf(acc[mt][nt][3]) + ms.y;
            float* p = g_scr + ((size_t)b * Oo + o) * Nn + n;
            *reinterpret_cast<float2*>(p) = v0;
            *reinterpret_cast<float2*>(p + 8 * Nn) = v1;
        }
}

// ---------------- kernel D: transpose scratch [d][r][o][n] -> out [n][d][o][r] ----------------
__global__ __launch_bounds__(256) void transpose_kernel(float* __restrict__ out) {
    extern __shared__ __align__(16) float tile[];  // [512][33], idx = o*16+r
    const int d = blockIdx.x >> 3;
    const int nb = blockIdx.x & 7;
    const int tid = threadIdx.x;
#pragma unroll
    for (int it = 0; it < 16; it++) {
        const int gidx = it * 256 + tid;          // 0..4095
        const int ro = gidx >> 3, s4 = gidx & 7;  // ro = r*32+o
        const float4 v = *reinterpret_cast<const float4*>(
            g_scr + ((size_t)(d * 512 + ro)) * Nn + nb * 32 + s4 * 4);
        const int idx = (ro & 31) * 16 + (ro >> 5);  // o*16 + r
        float* t = &tile[idx * 33 + s4 * 4];
        t[0] = v.x; t[1] = v.y; t[2] = v.z; t[3] = v.w;
    }
    __syncthreads();
#pragma unroll
    for (int n = 0; n < 32; n++) {
        float* ob = out + ((size_t)(nb * 32 + n) * Dd + d) * 512;
        ob[tid] = tile[tid * 33 + n];
        ob[tid + 256] = tile[(tid + 256) * 33 + n];
    }
}

extern "C" void kernel_launch(void* const* d_in, const int* in_sizes, int n_in,
                              void* d_out, int out_size) {
    const float* left = (const float*)d_in[0];
    const float* right = (const float*)d_in[1];
    const float* logits = (const float*)d_in[2];
    float* out = (float*)d_out;

    prep_kernel<<<Nn * Dd / 4, 128>>>(left, right);
    cudaFuncSetAttribute(einsum_mma_kernel, cudaFuncAttributeMaxDynamicSharedMemorySize, 32 * WSTRIDE * 2);
    einsum_mma_kernel<<<Dd * Rr, 512, 32 * WSTRIDE * 2>>>(logits);
    cudaFuncSetAttribute(transpose_kernel, cudaFuncAttributeMaxDynamicSharedMemorySize, 512 * 33 * 4);
    transpose_kernel<<<Dd * 8, 256, 512 * 33 * 4>>>(out);
}

// round 10
// speedup vs baseline: 7.0131x; 1.0427x over previous
#include <cuda_runtime.h>
#include <cuda_fp16.h>
#include <cstdint>

#define Nn 256
#define Dd 64
#define Cc 32
#define Rr 16
#define Oo 32

// exp(x - rowmax), fp16, [d][r][n][c]
__device__ __half g_LpH[(size_t)Dd * Rr * Nn * Cc];
__device__ __half g_RpH[(size_t)Dd * Rr * Nn * Cc];
// lmax + rmax, [d][r][n]
__device__ float g_msum[Dd * Rr * Nn];
// log-prob scratch, [d][r][o][n]  (coalesced for the GEMM, transposed later; L2-resident)
__device__ float g_scr[(size_t)Dd * Rr * Oo * Nn];

// ---------------- kernel B: left/right -> rowmax-shifted exp (fp16) ----------------
__global__ __launch_bounds__(128) void prep_kernel(const float* __restrict__ left,
                                                   const float* __restrict__ right) {
    __shared__ float sL[4][Cc * 17], sR[4][Cc * 17];
    __shared__ float lmaxs[4][Rr], rmaxs[4][Rr];
    const int w = threadIdx.x >> 5;
    const int n = blockIdx.x >> 4;
    const int d = (blockIdx.x & 15) * 4 + w;
    const int c = threadIdx.x & 31;
    float lv[Rr], rv[Rr];
    const float4* lp = reinterpret_cast<const float4*>(left + ((size_t)(n * Dd + d) * Cc + c) * Rr);
    const float4* rp = reinterpret_cast<const float4*>(right + ((size_t)(n * Dd + d) * Cc + c) * Rr);
#pragma unroll
    for (int q = 0; q < 4; q++) {
        *reinterpret_cast<float4*>(&lv[q * 4]) = lp[q];
        *reinterpret_cast<float4*>(&rv[q * 4]) = rp[q];
    }
#pragma unroll
    for (int rr = 0; rr < Rr; rr++) { sL[w][c * 17 + rr] = lv[rr]; sR[w][c * 17 + rr] = rv[rr]; }
    __syncwarp();
    if (c < 16) {
        float m = -3.4e38f;
        for (int cc = 0; cc < Cc; cc++) m = fmaxf(m, sL[w][cc * 17 + c]);
        lmaxs[w][c] = m;
    } else {
        const int rr = c - 16;
        float m = -3.4e38f;
        for (int cc = 0; cc < Cc; cc++) m = fmaxf(m, sR[w][cc * 17 + rr]);
        rmaxs[w][rr] = m;
    }
    __syncwarp();
#pragma unroll
    for (int rr = 0; rr < Rr; rr++) {
        const size_t base = ((size_t)(d * Rr + rr) * Nn + n) * Cc + c;
        g_LpH[base] = __float2half_rn(__expf(lv[rr] - lmaxs[w][rr]));
        g_RpH[base] = __float2half_rn(__expf(rv[rr] - rmaxs[w][rr]));
    }
    if (c < 16) g_msum[(d * Rr + c) * Nn + n] = lmaxs[w][c] + rmaxs[w][c];
}

// ---------------- kernel C: warp-MMA batched GEMM, 8 warps x 32n (2x A reuse) ----------------
__device__ __forceinline__ uint32_t s2u(const void* p) {
    uint32_t a;
    asm("{ .reg .u64 t; cvta.to.shared.u64 t, %1; cvt.u32.u64 %0, t; }" : "=r"(a) : "l"(p));
    return a;
}
__device__ __forceinline__ void ldmx4(uint32_t* a, uint32_t addr) {
    asm volatile("ldmatrix.sync.aligned.m8n8.x4.shared.b16 {%0,%1,%2,%3}, [%4];"
                 : "=r"(a[0]), "=r"(a[1]), "=r"(a[2]), "=r"(a[3]) : "r"(addr));
}
__device__ __forceinline__ void mma16816(float* c, const uint32_t* a, uint32_t b0, uint32_t b1) {
    asm volatile(
        "mma.sync.aligned.m16n8k16.row.col.f32.f16.f16.f32 "
        "{%0,%1,%2,%3},{%4,%5,%6,%7},{%8,%9},{%0,%1,%2,%3};"
        : "+f"(c[0]), "+f"(c[1]), "+f"(c[2]), "+f"(c[3])
        : "r"(a[0]), "r"(a[1]), "r"(a[2]), "r"(a[3]), "r"(b0), "r"(b1));
}

#define WSTRIDE 1032   // halves per padded W row (2064 B)
#define LPSTRIDE 40    // halves per padded Lp row (80 B = 16B-aligned, conflict-free reads)
#define SMEM_EINSUM ((32 * WSTRIDE + Nn * LPSTRIDE) * 2)

__global__ __launch_bounds__(256) void einsum_mma_kernel(const float* __restrict__ logits) {
    extern __shared__ __align__(16) __half sm[];
    __half* smW = sm;                      // 32 x WSTRIDE
    __half* sLp = sm + 32 * WSTRIDE;       // Nn x LPSTRIDE
    const int tid = threadIdx.x;
    const int wid = tid >> 5;
    const int ln = tid & 31;
    const int b = blockIdx.x;  // d*16 + r
    const int r = b & 15;
    const int d = b >> 4;

    // ---- stage W: fused softmax of logits[d, o, r, :], 4 o-rows per warp ----
#pragma unroll
    for (int rr2 = 0; rr2 < 4; rr2++) {
        const int o = wid * 4 + rr2;
        const float4* src = reinterpret_cast<const float4*>(
            logits + (((size_t)(d * Oo + o) * Rr + r) << 10));
        float4 v[8];
#pragma unroll
        for (int u = 0; u < 8; u++) v[u] = src[u * 32 + ln];
        float m = -3.4e38f;
#pragma unroll
        for (int u = 0; u < 8; u++)
            m = fmaxf(m, fmaxf(fmaxf(v[u].x, v[u].y), fmaxf(v[u].z, v[u].w)));
#pragma unroll
        for (int t = 16; t; t >>= 1) m = fmaxf(m, __shfl_xor_sync(~0u, m, t));
        float s = 0.f;
#pragma unroll
        for (int u = 0; u < 8; u++) {
            v[u].x = __expf(v[u].x - m);
            v[u].y = __expf(v[u].y - m);
            v[u].z = __expf(v[u].z - m);
            v[u].w = __expf(v[u].w - m);
            s += (v[u].x + v[u].y) + (v[u].z + v[u].w);
        }
#pragma unroll
        for (int t = 16; t; t >>= 1) s += __shfl_xor_sync(~0u, s, t);
        const float inv = 1.0f / s;
#pragma unroll
        for (int u = 0; u < 8; u++) {
            const __half2 h0 = __floats2half2_rn(v[u].x * inv, v[u].y * inv);
            const __half2 h1 = __floats2half2_rn(v[u].z * inv, v[u].w * inv);
            uint2 wv;
            wv.x = *reinterpret_cast<const uint32_t*>(&h0);
            wv.y = *reinterpret_cast<const uint32_t*>(&h1);
            *reinterpret_cast<uint2*>(smW + o * WSTRIDE + (u * 32 + ln) * 4) = wv;
        }
    }

    // ---- stage Lp into padded smem: one n per thread (80B rows, 16B-aligned) ----
    {
        const uint4* src = reinterpret_cast<const uint4*>(g_LpH + ((size_t)b * Nn + tid) * Cc);
#pragma unroll
        for (int q = 0; q < 4; q++)
            *reinterpret_cast<uint4*>(sLp + tid * LPSTRIDE + q * 8) = src[q];
    }

    // ---- per-lane Rp operands: 4 n-tiles of 8 ----
    const int wb = wid * 32;
    int nn[4];
    __half2 rp[4][4];
#pragma unroll
    for (int nt = 0; nt < 4; nt++) {
        nn[nt] = wb + nt * 8 + (ln >> 2);
        const __half* rsrc = g_RpH + ((size_t)b * Nn + nn[nt]) * Cc + (ln & 3) * 2;
#pragma unroll
        for (int q = 0; q < 4; q++)
            rp[nt][q] = *reinterpret_cast<const __half2*>(rsrc + q * 8);
    }
    __syncthreads();

    float acc[2][4][4];
#pragma unroll
    for (int mt = 0; mt < 2; mt++)
#pragma unroll
        for (int nt = 0; nt < 4; nt++)
#pragma unroll
            for (int q = 0; q < 4; q++) acc[mt][nt][q] = 0.f;

    const uint32_t abase = s2u(smW) + ((uint32_t)(ln & 15) * WSTRIDE + (uint32_t)((ln >> 4) & 1) * 8) * 2;

    __half2 lph2[4];
#pragma unroll 8
    for (int kc = 0; kc < 64; kc++) {  // k16-tile: i = kc>>1, j0 = (kc&1)*16
        if ((kc & 3) == 0) {
#pragma unroll
            for (int nt = 0; nt < 4; nt++)
                lph2[nt] = *reinterpret_cast<const __half2*>(sLp + nn[nt] * LPSTRIDE + (kc >> 1));
        }
        uint32_t a0[4], a1[4];
        ldmx4(a0, abase + (uint32_t)kc * 32);
        ldmx4(a1, abase + 16u * WSTRIDE * 2u + (uint32_t)kc * 32);
        const int q0 = (kc & 1) * 2;
#pragma unroll
        for (int nt = 0; nt < 4; nt++) {
            const __half h = ((kc >> 1) & 1) ? __high2half(lph2[nt]) : __low2half(lph2[nt]);
            const __half2 l2 = __half2half2(h);
            const __half2 b0 = __hmul2(rp[nt][q0], l2);
            const __half2 b1 = __hmul2(rp[nt][q0 + 1], l2);
            const uint32_t u0 = *reinterpret_cast<const uint32_t*>(&b0);
            const uint32_t u1 = *reinterpret_cast<const uint32_t*>(&b1);
            mma16816(acc[0][nt], a0, u0, u1);
            mma16816(acc[1][nt], a1, u0, u1);
        }
    }

    // ---- epilogue: log + msum, write scratch [b][o][n] (n-coalesced) ----
#pragma unroll
    for (int mt = 0; mt < 2; mt++)
#pragma unroll
        for (int nt = 0; nt < 4; nt++) {
            const int o = mt * 16 + (ln >> 2);
            const int n = wb + nt * 8 + (ln & 3) * 2;
            const float2 ms = *reinterpret_cast<const float2*>(&g_msum[b * Nn + n]);
            float2 v0, v1;
            v0.x = __logf(acc[mt][nt][0]) + ms.x;
            v0.y = __logf(acc[mt][nt][1]) + ms.y;
            v1.x = __logf(acc[mt][nt][2]) + ms.x;
            v1.y = __logf(acc[mt][nt][3]) + ms.y;
            float* p = g_scr + ((size_t)b * Oo + o) * Nn + n;
            *reinterpret_cast<float2*>(p) = v0;
            *reinterpret_cast<float2*>(p + 8 * Nn) = v1;
        }
}

// ---------------- kernel D: transpose scratch [d][r][o][n] -> out [n][d][o][r] ----------------
__global__ __launch_bounds__(256) void transpose_kernel(float* __restrict__ out) {
    __shared__ __align__(16) float tile[512 * 17];  // idx = o*16+r, 16 n per CTA
    const int d = blockIdx.x >> 4;
    const int nb = blockIdx.x & 15;
    const int tid = threadIdx.x;
#pragma unroll
    for (int it = 0; it < 8; it++) {
        const int gidx = it * 256 + tid;          // 0..2047
        const int ro = gidx >> 2, s4 = gidx & 3;  // ro = r*32+o
        const float4 v = *reinterpret_cast<const float4*>(
            g_scr + ((size_t)(d * 512 + ro)) * Nn + nb * 16 + s4 * 4);
        const int idx = (ro & 31) * 16 + (ro >> 5);  // o*16 + r
        float* t = &tile[idx * 17 + s4 * 4];
        t[0] = v.x; t[1] = v.y; t[2] = v.z; t[3] = v.w;
    }
    __syncthreads();
#pragma unroll
    for (int n = 0; n < 16; n++) {
        float* ob = out + ((size_t)(nb * 16 + n) * Dd + d) * 512;
        ob[tid] = tile[tid * 17 + n];
        ob[tid + 256] = tile[(tid + 256) * 17 + n];
    }
}

extern "C" void kernel_launch(void* const* d_in, const int* in_sizes, int n_in,
                              void* d_out, int out_size) {
    const float* left = (const float*)d_in[0];
    const float* right = (const float*)d_in[1];
    const float* logits = (const float*)d_in[2];
    float* out = (float*)d_out;

    prep_kernel<<<Nn * Dd / 4, 128>>>(left, right);
    cudaFuncSetAttribute(einsum_mma_kernel, cudaFuncAttributeMaxDynamicSharedMemorySize, SMEM_EINSUM);
    einsum_mma_kernel<<<Dd * Rr, 256, SMEM_EINSUM>>>(logits);
    transpose_kernel<<<Dd * 16, 256>>>(out);
}

// round 11
// speedup vs baseline: 7.1418x; 1.0183x over previous
#include <cuda_runtime.h>
#include <cuda_fp16.h>
#include <cstdint>

#define Nn 256
#define Dd 64
#define Cc 32
#define Rr 16
#define Oo 32

// exp(x - rowmax), fp16, [d][r][n][c]
__device__ __half g_LpH[(size_t)Dd * Rr * Nn * Cc];
__device__ __half g_RpH[(size_t)Dd * Rr * Nn * Cc];
// lmax + rmax, [d][r][n]
__device__ float g_msum[Dd * Rr * Nn];
// log-prob scratch, [d][r][o][n]  (coalesced for the GEMM, transposed later; L2-resident)
__device__ float g_scr[(size_t)Dd * Rr * Oo * Nn];

// ---------------- kernel B: left/right -> rowmax-shifted exp (fp16) ----------------
__global__ __launch_bounds__(128) void prep_kernel(const float* __restrict__ left,
                                                   const float* __restrict__ right) {
    __shared__ float sL[4][Cc * 17], sR[4][Cc * 17];
    __shared__ float lmaxs[4][Rr], rmaxs[4][Rr];
    const int w = threadIdx.x >> 5;
    const int n = blockIdx.x >> 4;
    const int d = (blockIdx.x & 15) * 4 + w;
    const int c = threadIdx.x & 31;
    float lv[Rr], rv[Rr];
    const float4* lp = reinterpret_cast<const float4*>(left + ((size_t)(n * Dd + d) * Cc + c) * Rr);
    const float4* rp = reinterpret_cast<const float4*>(right + ((size_t)(n * Dd + d) * Cc + c) * Rr);
#pragma unroll
    for (int q = 0; q < 4; q++) {
        *reinterpret_cast<float4*>(&lv[q * 4]) = lp[q];
        *reinterpret_cast<float4*>(&rv[q * 4]) = rp[q];
    }
#pragma unroll
    for (int rr = 0; rr < Rr; rr++) { sL[w][c * 17 + rr] = lv[rr]; sR[w][c * 17 + rr] = rv[rr]; }
    __syncwarp();
    if (c < 16) {
        float m = -3.4e38f;
        for (int cc = 0; cc < Cc; cc++) m = fmaxf(m, sL[w][cc * 17 + c]);
        lmaxs[w][c] = m;
    } else {
        const int rr = c - 16;
        float m = -3.4e38f;
        for (int cc = 0; cc < Cc; cc++) m = fmaxf(m, sR[w][cc * 17 + rr]);
        rmaxs[w][rr] = m;
    }
    __syncwarp();
#pragma unroll
    for (int rr = 0; rr < Rr; rr++) {
        const size_t base = ((size_t)(d * Rr + rr) * Nn + n) * Cc + c;
        g_LpH[base] = __float2half_rn(__expf(lv[rr] - lmaxs[w][rr]));
        g_RpH[base] = __float2half_rn(__expf(rv[rr] - rmaxs[w][rr]));
    }
    if (c < 16) g_msum[(d * Rr + c) * Nn + n] = lmaxs[w][c] + rmaxs[w][c];
}

// ---------------- kernel C: warp-MMA batched GEMM, 8 warps x 32n (2x A reuse) ----------------
__device__ __forceinline__ uint32_t s2u(const void* p) {
    uint32_t a;
    asm("{ .reg .u64 t; cvta.to.shared.u64 t, %1; cvt.u32.u64 %0, t; }" : "=r"(a) : "l"(p));
    return a;
}
__device__ __forceinline__ void ldmx4(uint32_t* a, uint32_t addr) {
    asm volatile("ldmatrix.sync.aligned.m8n8.x4.shared.b16 {%0,%1,%2,%3}, [%4];"
                 : "=r"(a[0]), "=r"(a[1]), "=r"(a[2]), "=r"(a[3]) : "r"(addr));
}
__device__ __forceinline__ void mma16816(float* c, const uint32_t* a, uint32_t b0, uint32_t b1) {
    asm volatile(
        "mma.sync.aligned.m16n8k16.row.col.f32.f16.f16.f32 "
        "{%0,%1,%2,%3},{%4,%5,%6,%7},{%8,%9},{%0,%1,%2,%3};"
        : "+f"(c[0]), "+f"(c[1]), "+f"(c[2]), "+f"(c[3])
        : "r"(a[0]), "r"(a[1]), "r"(a[2]), "r"(a[3]), "r"(b0), "r"(b1));
}

#define WSTRIDE 1032   // halves per padded W row (2064 B)
#define LPSTRIDE 40    // halves per padded Lp row (80 B = 16B-aligned, conflict-free reads)
#define SMEM_EINSUM ((32 * WSTRIDE + Nn * LPSTRIDE) * 2)

__global__ __launch_bounds__(256) void einsum_mma_kernel(const float* __restrict__ logits) {
    extern __shared__ __align__(16) __half sm[];
    __half* smW = sm;                      // 32 x WSTRIDE
    __half* sLp = sm + 32 * WSTRIDE;       // Nn x LPSTRIDE
    const int tid = threadIdx.x;
    const int wid = tid >> 5;
    const int ln = tid & 31;
    const int b = blockIdx.x;  // d*16 + r
    const int r = b & 15;
    const int d = b >> 4;

    // ---- stage W: fused softmax of logits[d, o, r, :], 4 o-rows per warp ----
#pragma unroll
    for (int rr2 = 0; rr2 < 4; rr2++) {
        const int o = wid * 4 + rr2;
        const float4* src = reinterpret_cast<const float4*>(
            logits + (((size_t)(d * Oo + o) * Rr + r) << 10));
        float4 v[8];
#pragma unroll
        for (int u = 0; u < 8; u++) v[u] = src[u * 32 + ln];
        float m = -3.4e38f;
#pragma unroll
        for (int u = 0; u < 8; u++)
            m = fmaxf(m, fmaxf(fmaxf(v[u].x, v[u].y), fmaxf(v[u].z, v[u].w)));
#pragma unroll
        for (int t = 16; t; t >>= 1) m = fmaxf(m, __shfl_xor_sync(~0u, m, t));
        float s = 0.f;
#pragma unroll
        for (int u = 0; u < 8; u++) {
            v[u].x = __expf(v[u].x - m);
            v[u].y = __expf(v[u].y - m);
            v[u].z = __expf(v[u].z - m);
            v[u].w = __expf(v[u].w - m);
            s += (v[u].x + v[u].y) + (v[u].z + v[u].w);
        }
#pragma unroll
        for (int t = 16; t; t >>= 1) s += __shfl_xor_sync(~0u, s, t);
        const float inv = 1.0f / s;
#pragma unroll
        for (int u = 0; u < 8; u++) {
            const __half2 h0 = __floats2half2_rn(v[u].x * inv, v[u].y * inv);
            const __half2 h1 = __floats2half2_rn(v[u].z * inv, v[u].w * inv);
            uint2 wv;
            wv.x = *reinterpret_cast<const uint32_t*>(&h0);
            wv.y = *reinterpret_cast<const uint32_t*>(&h1);
            *reinterpret_cast<uint2*>(smW + o * WSTRIDE + (u * 32 + ln) * 4) = wv;
        }
    }

    // ---- stage Lp into padded smem: one n per thread (80B rows, 16B-aligned) ----
    {
        const uint4* src = reinterpret_cast<const uint4*>(g_LpH + ((size_t)b * Nn + tid) * Cc);
#pragma unroll
        for (int q = 0; q < 4; q++)
            *reinterpret_cast<uint4*>(sLp + tid * LPSTRIDE + q * 8) = src[q];
    }

    // ---- per-lane Rp operands: 4 n-tiles of 8 ----
    const int wb = wid * 32;
    int nn[4];
    __half2 rp[4][4];
#pragma unroll
    for (int nt = 0; nt < 4; nt++) {
        nn[nt] = wb + nt * 8 + (ln >> 2);
        const __half* rsrc = g_RpH + ((size_t)b * Nn + nn[nt]) * Cc + (ln & 3) * 2;
#pragma unroll
        for (int q = 0; q < 4; q++)
            rp[nt][q] = *reinterpret_cast<const __half2*>(rsrc + q * 8);
    }
    __syncthreads();

    float acc[2][4][4];
#pragma unroll
    for (int mt = 0; mt < 2; mt++)
#pragma unroll
        for (int nt = 0; nt < 4; nt++)
#pragma unroll
            for (int q = 0; q < 4; q++) acc[mt][nt][q] = 0.f;

    const uint32_t abase = s2u(smW) + ((uint32_t)(ln & 15) * WSTRIDE + (uint32_t)((ln >> 4) & 1) * 8) * 2;

    __half2 lph2[4];
#pragma unroll 8
    for (int kc = 0; kc < 64; kc++) {  // k16-tile: i = kc>>1, j0 = (kc&1)*16
        if ((kc & 3) == 0) {
#pragma unroll
            for (int nt = 0; nt < 4; nt++)
                lph2[nt] = *reinterpret_cast<const __half2*>(sLp + nn[nt] * LPSTRIDE + (kc >> 1));
        }
        uint32_t a0[4], a1[4];
        ldmx4(a0, abase + (uint32_t)kc * 32);
        ldmx4(a1, abase + 16u * WSTRIDE * 2u + (uint32_t)kc * 32);
        const int q0 = (kc & 1) * 2;
#pragma unroll
        for (int nt = 0; nt < 4; nt++) {
            const __half h = ((kc >> 1) & 1) ? __high2half(lph2[nt]) : __low2half(lph2[nt]);
            const __half2 l2 = __half2half2(h);
            const __half2 b0 = __hmul2(rp[nt][q0], l2);
            const __half2 b1 = __hmul2(rp[nt][q0 + 1], l2);
            const uint32_t u0 = *reinterpret_cast<const uint32_t*>(&b0);
            const uint32_t u1 = *reinterpret_cast<const uint32_t*>(&b1);
            mma16816(acc[0][nt], a0, u0, u1);
            mma16816(acc[1][nt], a1, u0, u1);
        }
    }

    // ---- epilogue: log + msum, write scratch [b][o][n] (n-coalesced) ----
#pragma unroll
    for (int mt = 0; mt < 2; mt++)
#pragma unroll
        for (int nt = 0; nt < 4; nt++) {
            const int o = mt * 16 + (ln >> 2);
            const int n = wb + nt * 8 + (ln & 3) * 2;
            const float2 ms = *reinterpret_cast<const float2*>(&g_msum[b * Nn + n]);
            float2 v0, v1;
            v0.x = __logf(acc[mt][nt][0]) + ms.x;
            v0.y = __logf(acc[mt][nt][1]) + ms.y;
            v1.x = __logf(acc[mt][nt][2]) + ms.x;
            v1.y = __logf(acc[mt][nt][3]) + ms.y;
            float* p = g_scr + ((size_t)b * Oo + o) * Nn + n;
            *reinterpret_cast<float2*>(p) = v0;
            *reinterpret_cast<float2*>(p + 8 * Nn) = v1;
        }
}

// ---------------- kernel D: transpose scratch [d][r][o][n] -> out [n][d][o][r] ----------------
__global__ __launch_bounds__(256) void transpose_kernel(float* __restrict__ out) {
    __shared__ __align__(16) float tile[512 * 17];  // idx = o*16+r, 16 n per CTA
    const int d = blockIdx.x >> 4;
    const int nb = blockIdx.x & 15;
    const int tid = threadIdx.x;
#pragma unroll
    for (int it = 0; it < 8; it++) {
        const int gidx = it * 256 + tid;          // 0..2047
        const int ro = gidx >> 2, s4 = gidx & 3;  // ro = r*32+o
        const float4 v = *reinterpret_cast<const float4*>(
            g_scr + ((size_t)(d * 512 + ro)) * Nn + nb * 16 + s4 * 4);
        const int idx = (ro & 31) * 16 + (ro >> 5);  // o*16 + r
        float* t = &tile[idx * 17 + s4 * 4];
        t[0] = v.x; t[1] = v.y; t[2] = v.z; t[3] = v.w;
    }
    __syncthreads();
#pragma unroll
    for (int n = 0; n < 16; n++) {
        float* ob = out + ((size_t)(nb * 16 + n) * Dd + d) * 512;
        ob[tid] = tile[tid * 17 + n];
        ob[tid + 256] = tile[(tid + 256) * 17 + n];
    }
}

extern "C" void kernel_launch(void* const* d_in, const int* in_sizes, int n_in,
                              void* d_out, int out_size) {
    const float* left = (const float*)d_in[0];
    const float* right = (const float*)d_in[1];
    const float* logits = (const float*)d_in[2];
    float* out = (float*)d_out;

    prep_kernel<<<Nn * Dd / 4, 128>>>(left, right);
    cudaFuncSetAttribute(einsum_mma_kernel, cudaFuncAttributeMaxDynamicSharedMemorySize, SMEM_EINSUM);
    einsum_mma_kernel<<<Dd * Rr, 256, SMEM_EINSUM>>>(logits);
    transpose_kernel<<<Dd * 16, 256>>>(out);
}